// round 15
// baseline (speedup 1.0000x reference)
#include <cuda_runtime.h>
#include <math.h>

// Problem: input (8, 64, 64, 3) fp32 -> scalar fp32.
// Spectral method: total = (1/128) Sum_dy w_dy Sum_k wk KhatD(dy,k) ReS(dy,k).
#define NB   8
#define W64  64
#define NPIX 4096
#define NELE 32768
#define NR   512              // rows = NB * 64
#define NKB  65               // spectral bins 0..64 (real-input symmetry)
#define PRE_BLKS 128          // 64 input blocks + 64 Khat blocks
#define DFT_BLKS 64
#define CORR_BLKS 65

// ---- scratch (no allocations allowed -> __device__ globals) ----
__device__ __align__(16) float  g_a[NELE];        // |x|.sum(-1), rows [b][iy][ix]
__device__ __align__(16) float2 g_F[NKB * NR];    // spectra, [k][row]
__device__ __align__(16) float  g_Khat[64 * NKB]; // w_dy * DFT(kernel row dy)
__device__ unsigned int g_minbits = 0x7F800000u;  // +inf (a >= 0 -> uint order ok)
__device__ unsigned int g_maxbits = 0u;
__device__ double       g_partc[CORR_BLKS];
__device__ unsigned int g_cnt = 0;                // self-resetting counter

// ---------------------------------------------------------------
// Blocks 0..63: abs-sum rows + global min/max (uint-bit atomics).
// Blocks 64..127: Khat for dy = bid-64 (data-independent).
__global__ void __launch_bounds__(128) k_pre(const float4* __restrict__ in4) {
    int tid = threadIdx.x;
    int bid = blockIdx.x;

    if (bid < 64) {
        int t = bid * 128 + tid;                       // 0..8191
        float4 a = in4[t * 3 + 0];
        float4 b = in4[t * 3 + 1];
        float4 c = in4[t * 3 + 2];

        float4 s;
        s.x = fabsf(a.x) + fabsf(a.y) + fabsf(a.z);
        s.y = fabsf(a.w) + fabsf(b.x) + fabsf(b.y);
        s.z = fabsf(b.z) + fabsf(b.w) + fabsf(c.x);
        s.w = fabsf(c.y) + fabsf(c.z) + fabsf(c.w);
        *(float4*)&g_a[t * 4] = s;

        float mn = fminf(fminf(s.x, s.y), fminf(s.z, s.w));
        float mx = fmaxf(fmaxf(s.x, s.y), fmaxf(s.z, s.w));
        #pragma unroll
        for (int o = 16; o; o >>= 1) {
            mn = fminf(mn, __shfl_xor_sync(0xffffffffu, mn, o));
            mx = fmaxf(mx, __shfl_xor_sync(0xffffffffu, mx, o));
        }
        __shared__ float smn[4], smx[4];
        int wid = tid >> 5, lid = tid & 31;
        if (lid == 0) { smn[wid] = mn; smx[wid] = mx; }
        __syncthreads();
        if (tid == 0) {
            #pragma unroll
            for (int w = 1; w < 4; w++) { mn = fminf(mn, smn[w]); mx = fmaxf(mx, smx[w]); }
            atomicMin(&g_minbits, __float_as_uint(mn));
            atomicMax(&g_maxbits, __float_as_uint(mx));
        }
    } else {
        // Khat_dy(k) = Sum_{n=0}^{127} K[n] cos(2*pi*n*k/128),
        // K[n] = sqrt(dy^2+dx^2), dx = n (n<64), n-128 (n>64), K[64]=0.
        int dy = bid - 64;
        __shared__ float s_d[64];
        if (tid < 64) s_d[tid] = sqrtf((float)(dy * dy + tid * tid));
        __syncthreads();
        if (tid < NKB) {
            int k = tid;
            float sw, cw;
            sincosf(0.049087385212340517f * (float)k, &sw, &cw);   // +2*pi*k/128
            float cr = 1.0f, ci = 0.0f, acc = 0.0f;
            #pragma unroll 8
            for (int n = 0; n < 128; n++) {
                float Kn = (n < 64) ? s_d[n] : ((n == 64) ? 0.0f : s_d[128 - n]);
                acc = fmaf(Kn, cr, acc);
                float t1 = cr * cw - ci * sw;
                float t2 = cr * sw + ci * cw;
                cr = t1; ci = t2;
            }
            float wdy = (dy == 0) ? 1.0f : 2.0f;       // dy<0 mirror (kernel even in dx)
            g_Khat[dy * NKB + k] = wdy * acc;
        }
    }
}

// ---------------------------------------------------------------
// Row DFTs. 64 blocks x 512 threads; block = 8 rows x 64 bins.
// F(k) = Sum_{x=0}^{63} f[x] e^{-2*pi*i*k*x/128} via rotation recurrence.
// Bin 64 (Nyquist) computed by the k==0 threads: Sum (-1)^x f[x].
__global__ void __launch_bounds__(512) k_dft() {
    __shared__ float s_f[512];                         // 8 rows x 64, normalized

    int tid = threadIdx.x;
    int r0  = blockIdx.x * 8;

    asm volatile("griddepcontrol.wait;" ::: "memory"); // k_pre done

    float mn  = __uint_as_float(g_minbits);
    float mx  = __uint_as_float(g_maxbits);
    float inv = 1.0f / (mx - mn);
    float nb  = -mn * inv;

    s_f[tid] = fmaf(g_a[r0 * 64 + tid], inv, nb);      // 512 contiguous floats
    __syncthreads();

    int ridx = tid >> 6;                               // local row 0..7
    int k    = tid & 63;                               // bin 0..63
    const float* fr = s_f + ridx * 64;

    float sw, cw;
    sincosf(-0.049087385212340517f * (float)k, &sw, &cw);  // e^{-2*pi*i*k/128}
    float cr = 1.0f, ci = 0.0f, are = 0.0f, aim = 0.0f;
    #pragma unroll 16
    for (int x = 0; x < 64; x++) {
        float fv = fr[x];
        are = fmaf(fv, cr, are);
        aim = fmaf(fv, ci, aim);
        float t1 = cr * cw - ci * sw;
        float t2 = cr * sw + ci * cw;
        cr = t1; ci = t2;
    }
    g_F[k * NR + (r0 + ridx)] = make_float2(are, aim);

    if (k == 0) {                                      // Nyquist bin
        float s = 0.0f;
        #pragma unroll 16
        for (int x = 0; x < 64; x += 2) s += fr[x] - fr[x + 1];
        g_F[64 * NR + (r0 + ridx)] = make_float2(s, 0.0f);
    }
}

// ---------------------------------------------------------------
// Correlation + contraction. 65 blocks (one k-bin) x 256 threads.
// ReS_dy(k) = Sum_{b, iy<64-dy} F1.re*F2.re + F1.im*F2.im  (F2 = row iy+dy),
// block scalar = wk * Sum_dy Khat[dy][k] * ReS_dy(k); last block reduces.
__global__ void __launch_bounds__(256) k_corr(float* __restrict__ out) {
    __shared__ __align__(8) float2 s_F[NR];            // this bin's spectra slab, 4KB
    __shared__ float  s_p[256];
    __shared__ double s_red[8];
    __shared__ bool   s_last;

    int tid = threadIdx.x;
    int k   = blockIdx.x;
    int lane = tid & 31, wid = tid >> 5;

    asm volatile("griddepcontrol.wait;" ::: "memory"); // k_dft done

    s_F[tid]       = g_F[k * NR + tid];
    s_F[tid + 256] = g_F[k * NR + tid + 256];
    __syncthreads();

    int dy = tid & 63;
    int h  = tid >> 6;                                 // iy quarter 0..3
    int iy_lo = h * 16;
    int iy_hi = min(iy_lo + 16, 64 - dy);

    float acc = 0.0f;
    #pragma unroll
    for (int b = 0; b < 8; b++) {
        int base = b * 64;
        for (int iy = iy_lo; iy < iy_hi; iy++) {
            float2 F1 = s_F[base + iy];
            float2 F2 = s_F[base + iy + dy];
            acc = fmaf(F1.x, F2.x, acc);
            acc = fmaf(F1.y, F2.y, acc);
        }
    }
    s_p[tid] = acc;
    __syncthreads();

    double pv = 0.0;
    if (tid < 64) {
        float v = s_p[tid] + s_p[tid + 64] + s_p[tid + 128] + s_p[tid + 192];
        pv = (double)g_Khat[tid * NKB + k] * (double)v;   // tid = dy
    }
    if (tid < 64) {
        #pragma unroll
        for (int o = 16; o; o >>= 1)
            pv += __shfl_xor_sync(0xffffffffu, pv, o);
        if (lane == 0) s_red[wid] = pv;
    }
    __syncthreads();
    if (tid == 0) {
        float wk = (k == 0 || k == 64) ? 1.0f : 2.0f;   // conjugate-symmetry weight
        g_partc[k] = (s_red[0] + s_red[1]) * (double)wk;
        __threadfence();
        s_last = (atomicAdd(&g_cnt, 1u) == CORR_BLKS - 1u);
    }
    __syncthreads();

    // ---- last block: fixed-order reduce over the 65 bin scalars ----
    if (s_last) {
        double s = (tid < CORR_BLKS) ? ((volatile double*)g_partc)[tid] : 0.0;
        #pragma unroll
        for (int o = 16; o; o >>= 1)
            s += __shfl_xor_sync(0xffffffffu, s, o);
        if (lane == 0) s_red[wid] = s;
        __syncthreads();
        if (tid == 0) {
            double t = 0.0;
            #pragma unroll
            for (int w = 0; w < 8; w++) t += s_red[w];
            // / 128 (Parseval) / (B*N*N = 134217728)
            out[0] = (float)(t * (1.0 / (128.0 * 134217728.0)));
            g_cnt     = 0;                              // reset for graph replay
            g_minbits = 0x7F800000u;
            g_maxbits = 0u;
        }
    }
}

extern "C" void kernel_launch(void* const* d_in, const int* in_sizes, int n_in,
                              void* d_out, int out_size) {
    const float4* in4 = (const float4*)d_in[0];
    float*        out = (float*)d_out;

    k_pre<<<PRE_BLKS, 128>>>(in4);

    cudaLaunchAttribute attr[1];
    attr[0].id = cudaLaunchAttributeProgrammaticStreamSerialization;
    attr[0].val.programmaticStreamSerializationAllowed = 1;

    cudaLaunchConfig_t cfg1 = {};
    cfg1.gridDim  = dim3(DFT_BLKS);
    cfg1.blockDim = dim3(512);
    cfg1.attrs    = attr;
    cfg1.numAttrs = 1;
    cudaLaunchKernelEx(&cfg1, k_dft);

    cudaLaunchConfig_t cfg2 = {};
    cfg2.gridDim  = dim3(CORR_BLKS);
    cfg2.blockDim = dim3(256);
    cfg2.attrs    = attr;
    cfg2.numAttrs = 1;
    cudaLaunchKernelEx(&cfg2, k_corr, out);
}

// round 16
// speedup vs baseline: 1.0019x; 1.0019x over previous
#include <cuda_runtime.h>
#include <math.h>

// Problem: input (8, 64, 64, 3) fp32 -> scalar fp32.
// Spectral method: total = (1/128) Sum_dy w_dy Sum_k wk Khat(dy,k) ReS(dy,k).
#define NB   8
#define NPIX 4096
#define NELE 32768
#define NR   512              // rows = NB * 64
#define NKB  65               // spectral bins 0..64 (real-input symmetry)
#define PRE_BLKS 64
#define DFT_BLKS 128
#define CORR_BLKS 65
#define STEP128 0.049087385212340517f   // 2*pi/128

// ---- scratch (no allocations allowed -> __device__ globals) ----
__device__ __align__(16) float  g_a[NELE];        // |x|.sum(-1), rows [b][iy][ix]
__device__ __align__(16) float2 g_F[NKB * NR];    // spectra, [k][row]
__device__ unsigned int g_minbits = 0x7F800000u;  // +inf (a >= 0 -> uint order ok)
__device__ unsigned int g_maxbits = 0u;
__device__ double       g_partc[CORR_BLKS];
__device__ unsigned int g_cnt = 0;                // self-resetting counter

__device__ __forceinline__ void rot(float& cr, float& ci, float cw, float sw) {
    float t1 = cr * cw - ci * sw;
    float t2 = cr * sw + ci * cw;
    cr = t1; ci = t2;
}

// ---------------------------------------------------------------
// Input only: abs-sum rows + global min/max (uint-bit atomics).
__global__ void __launch_bounds__(128) k_pre(const float4* __restrict__ in4) {
    int tid = threadIdx.x;
    int t = blockIdx.x * 128 + tid;                    // 0..8191
    float4 a = in4[t * 3 + 0];
    float4 b = in4[t * 3 + 1];
    float4 c = in4[t * 3 + 2];

    float4 s;
    s.x = fabsf(a.x) + fabsf(a.y) + fabsf(a.z);
    s.y = fabsf(a.w) + fabsf(b.x) + fabsf(b.y);
    s.z = fabsf(b.z) + fabsf(b.w) + fabsf(c.x);
    s.w = fabsf(c.y) + fabsf(c.z) + fabsf(c.w);
    *(float4*)&g_a[t * 4] = s;

    float mn = fminf(fminf(s.x, s.y), fminf(s.z, s.w));
    float mx = fmaxf(fmaxf(s.x, s.y), fmaxf(s.z, s.w));
    #pragma unroll
    for (int o = 16; o; o >>= 1) {
        mn = fminf(mn, __shfl_xor_sync(0xffffffffu, mn, o));
        mx = fmaxf(mx, __shfl_xor_sync(0xffffffffu, mx, o));
    }
    __shared__ float smn[4], smx[4];
    int wid = tid >> 5, lid = tid & 31;
    if (lid == 0) { smn[wid] = mn; smx[wid] = mx; }
    __syncthreads();
    if (tid == 0) {
        #pragma unroll
        for (int w = 1; w < 4; w++) { mn = fminf(mn, smn[w]); mx = fmaxf(mx, smx[w]); }
        atomicMin(&g_minbits, __float_as_uint(mn));
        atomicMax(&g_maxbits, __float_as_uint(mx));
    }
}

// ---------------------------------------------------------------
// Row DFTs. 128 blocks x 512 threads; block = 4 rows, 2 threads per (row, k)
// (x-sum split in halves, combined by shfl). F(k) = Sum_x f[x] e^{-i 2pi kx/128}.
// Bin 64 (Nyquist) by the (k=0, half=1) thread: alternating sum.
__global__ void __launch_bounds__(512) k_dft() {
    __shared__ float s_f[256];                         // 4 rows x 64, normalized

    int tid = threadIdx.x;
    int r0  = blockIdx.x * 4;

    asm volatile("griddepcontrol.wait;" ::: "memory"); // k_pre done

    float mn  = __uint_as_float(g_minbits);
    float mx  = __uint_as_float(g_maxbits);
    float inv = 1.0f / (mx - mn);
    float nb  = -mn * inv;

    if (tid < 256) s_f[tid] = fmaf(g_a[r0 * 64 + tid], inv, nb);
    __syncthreads();

    int ridx = tid >> 7;                               // local row 0..3
    int rem  = tid & 127;
    int k    = rem >> 1;                               // bin 0..63
    int half = rem & 1;                                // x half 0/1
    const float* fr = s_f + ridx * 64;

    float step = -STEP128 * (float)k;
    float sw, cw;
    sincosf(step, &sw, &cw);
    float ci, cr;
    sincosf(step * (float)(half * 32), &ci, &cr);      // phase at x0 = half*32

    float are = 0.0f, aim = 0.0f;
    int x0 = half * 32;
    #pragma unroll 16
    for (int j = 0; j < 32; j++) {
        float fv = fr[x0 + j];
        are = fmaf(fv, cr, are);
        aim = fmaf(fv, ci, aim);
        rot(cr, ci, cw, sw);
    }
    are += __shfl_xor_sync(0xffffffffu, are, 1);
    aim += __shfl_xor_sync(0xffffffffu, aim, 1);
    if (half == 0) g_F[k * NR + (r0 + ridx)] = make_float2(are, aim);

    if (rem == 1) {                                    // Nyquist bin
        float s = 0.0f;
        #pragma unroll 16
        for (int x = 0; x < 64; x += 2) s += fr[x] - fr[x + 1];
        g_F[64 * NR + (r0 + ridx)] = make_float2(s, 0.0f);
    }
}

// ---------------------------------------------------------------
// Correlation + contraction. 65 blocks (one k-bin each) x 256 threads.
// PRE-WAIT (overlaps k_pre/k_dft): this bin's Khat column, 4 threads per dy.
// POST-WAIT: ReS_dy(k) over row pairs with gap dy, contract with Khat, reduce.
__global__ void __launch_bounds__(256) k_corr(float* __restrict__ out) {
    __shared__ __align__(8) float2 s_F[NR];            // this bin's spectra, 4KB
    __shared__ float  s_K[64];
    __shared__ float  s_p[256];
    __shared__ double s_red[8];
    __shared__ bool   s_last;

    int tid  = threadIdx.x;
    int k    = blockIdx.x;
    int lane = tid & 31, wid = tid >> 5;

    // ---- DATA-INDEPENDENT: Khat_dy(k) = Sum_n K[n] cos(2pi k n/128) ----
    {
        int dy = tid >> 2, q = tid & 3;                // 4 threads per dy
        float step = STEP128 * (float)k;
        float sw, cw;
        sincosf(step, &sw, &cw);
        float ci, cr;
        sincosf(step * (float)(q * 32), &ci, &cr);

        float acc = 0.0f;
        int n0 = q * 32;
        #pragma unroll 8
        for (int j = 0; j < 32; j++) {
            int n   = n0 + j;
            int dxa = (n < 64) ? n : 128 - n;          // |dx|
            float Kn = (n == 64) ? 0.0f
                                 : sqrtf((float)(dy * dy + dxa * dxa));
            acc = fmaf(Kn, cr, acc);
            rot(cr, ci, cw, sw);
        }
        s_p[tid] = acc;
    }
    __syncthreads();
    if (tid < 64) {
        float kv = s_p[tid * 4] + s_p[tid * 4 + 1]
                 + s_p[tid * 4 + 2] + s_p[tid * 4 + 3];
        s_K[tid] = ((tid == 0) ? 1.0f : 2.0f) * kv;    // w_dy (kernel even in dx)
    }

    // ---- wait for spectra ----
    asm volatile("griddepcontrol.wait;" ::: "memory");

    s_F[tid]       = g_F[k * NR + tid];
    s_F[tid + 256] = g_F[k * NR + tid + 256];
    __syncthreads();                                   // also fences s_K / s_p reuse

    int dy = tid & 63;
    int h  = tid >> 6;                                 // iy quarter 0..3
    int iy_lo = h * 16;
    int iy_hi = min(iy_lo + 16, 64 - dy);

    float acc = 0.0f;
    #pragma unroll
    for (int b = 0; b < 8; b++) {
        int base = b * 64;
        for (int iy = iy_lo; iy < iy_hi; iy++) {
            float2 F1 = s_F[base + iy];
            float2 F2 = s_F[base + iy + dy];
            acc = fmaf(F1.x, F2.x, acc);
            acc = fmaf(F1.y, F2.y, acc);
        }
    }
    s_p[tid] = acc;
    __syncthreads();

    double pv = 0.0;
    if (tid < 64) {
        float v = s_p[tid] + s_p[tid + 64] + s_p[tid + 128] + s_p[tid + 192];
        pv = (double)s_K[tid] * (double)v;             // tid = dy
        #pragma unroll
        for (int o = 16; o; o >>= 1)
            pv += __shfl_xor_sync(0xffffffffu, pv, o);
        if (lane == 0) s_red[wid] = pv;
    }
    __syncthreads();
    if (tid == 0) {
        float wk = (k == 0 || k == 64) ? 1.0f : 2.0f;  // conjugate-symmetry weight
        g_partc[k] = (s_red[0] + s_red[1]) * (double)wk;
        __threadfence();
        s_last = (atomicAdd(&g_cnt, 1u) == CORR_BLKS - 1u);
    }
    __syncthreads();

    // ---- last block: fixed-order reduce over the 65 bin scalars ----
    if (s_last) {
        double s = (tid < CORR_BLKS) ? ((volatile double*)g_partc)[tid] : 0.0;
        #pragma unroll
        for (int o = 16; o; o >>= 1)
            s += __shfl_xor_sync(0xffffffffu, s, o);
        if (lane == 0) s_red[wid] = s;
        __syncthreads();
        if (tid == 0) {
            double t = 0.0;
            #pragma unroll
            for (int w = 0; w < 8; w++) t += s_red[w];
            // / 128 (Parseval) / (B*N*N = 134217728)
            out[0] = (float)(t * (1.0 / (128.0 * 134217728.0)));
            g_cnt     = 0;                              // reset for graph replay
            g_minbits = 0x7F800000u;
            g_maxbits = 0u;
        }
    }
}

extern "C" void kernel_launch(void* const* d_in, const int* in_sizes, int n_in,
                              void* d_out, int out_size) {
    const float4* in4 = (const float4*)d_in[0];
    float*        out = (float*)d_out;

    k_pre<<<PRE_BLKS, 128>>>(in4);

    cudaLaunchAttribute attr[1];
    attr[0].id = cudaLaunchAttributeProgrammaticStreamSerialization;
    attr[0].val.programmaticStreamSerializationAllowed = 1;

    cudaLaunchConfig_t cfg1 = {};
    cfg1.gridDim  = dim3(DFT_BLKS);
    cfg1.blockDim = dim3(512);
    cfg1.attrs    = attr;
    cfg1.numAttrs = 1;
    cudaLaunchKernelEx(&cfg1, k_dft);

    cudaLaunchConfig_t cfg2 = {};
    cfg2.gridDim  = dim3(CORR_BLKS);
    cfg2.blockDim = dim3(256);
    cfg2.attrs    = attr;
    cfg2.numAttrs = 1;
    cudaLaunchKernelEx(&cfg2, k_corr, out);
}

// round 17
// speedup vs baseline: 1.0171x; 1.0152x over previous
#include <cuda_runtime.h>
#include <math.h>

// Problem: input (8, 64, 64, 3) fp32 -> scalar fp32.
// Spectral method: total = (1/128) Sum_dy w_dy Sum_k wk Khat(dy,k) ReS(dy,k).
#define NB   8
#define NPIX 4096
#define NELE 32768
#define NR   512              // rows = NB * 64
#define NKB  65               // spectral bins 0..64 (real-input symmetry)
#define PRE_BLKS  128         // 64 threads each
#define SPEC_BLKS 128
#define STEP128 0.049087385212340517f   // 2*pi/128

// ---- scratch (no allocations allowed -> __device__ globals) ----
__device__ __align__(16) float  g_a[NELE];        // |x|.sum(-1), rows [b][iy][ix]
__device__ __align__(16) float  g_dtab[4096];     // sqrt(dy^2+dx^2), [dy][dx]
__device__ __align__(16) float2 g_F[NKB * NR];    // spectra, [k][row]
__device__ unsigned int g_minbits = 0x7F800000u;  // +inf (a >= 0 -> uint order ok)
__device__ unsigned int g_maxbits = 0u;
__device__ double       g_partc[NKB];
__device__ unsigned int g_cnt_dft = 0;            // self-resetting counters
__device__ unsigned int g_cnt_fin = 0;

__device__ __forceinline__ void rot(float& cr, float& ci, float cw, float sw) {
    float t1 = cr * cw - ci * sw;
    float t2 = cr * sw + ci * cw;
    cr = t1; ci = t2;
}

// ---------------------------------------------------------------
// Input abs-sum + global min/max + distance table. 128 blocks x 64 threads.
__global__ void __launch_bounds__(64) k_pre(const float4* __restrict__ in4) {
    int tid = threadIdx.x;
    int t   = blockIdx.x * 64 + tid;                   // 0..8191
    float4 a = in4[t * 3 + 0];
    float4 b = in4[t * 3 + 1];
    float4 c = in4[t * 3 + 2];

    // distance table (first 4096 threads): one MUFU each
    if (t < 4096) {
        int dy = t >> 6, dx = t & 63;
        g_dtab[t] = sqrtf((float)(dy * dy + dx * dx));
    }

    float4 s;
    s.x = fabsf(a.x) + fabsf(a.y) + fabsf(a.z);
    s.y = fabsf(a.w) + fabsf(b.x) + fabsf(b.y);
    s.z = fabsf(b.z) + fabsf(b.w) + fabsf(c.x);
    s.w = fabsf(c.y) + fabsf(c.z) + fabsf(c.w);
    *(float4*)&g_a[t * 4] = s;

    float mn = fminf(fminf(s.x, s.y), fminf(s.z, s.w));
    float mx = fmaxf(fmaxf(s.x, s.y), fmaxf(s.z, s.w));
    #pragma unroll
    for (int o = 16; o; o >>= 1) {
        mn = fminf(mn, __shfl_xor_sync(0xffffffffu, mn, o));
        mx = fmaxf(mx, __shfl_xor_sync(0xffffffffu, mx, o));
    }
    __shared__ float smn[2], smx[2];
    int wid = tid >> 5, lid = tid & 31;
    if (lid == 0) { smn[wid] = mn; smx[wid] = mx; }
    __syncthreads();
    if (tid == 0) {
        mn = fminf(mn, smn[1]);
        mx = fmaxf(mx, smx[1]);
        atomicMin(&g_minbits, __float_as_uint(mn));
        atomicMax(&g_maxbits, __float_as_uint(mx));
    }
}

// ---------------------------------------------------------------
// Fused spectral kernel. 128 blocks x 512 threads (one wave; all resident).
// Phase B (all blocks): DFT of 4 rows -> g_F, fence, counter.
// Blocks >= 65 exit. Blocks 0..64 (bin k = bid):
//   Khat column from g_dtab (overlaps other blocks' DFT), spin on counter,
//   slab-load spectra, correlate over row pairs, contract, reduce.
__global__ void __launch_bounds__(512) k_spec(float* __restrict__ out) {
    __shared__ float  s_f[256];                        // 4 rows x 64, normalized
    __shared__ __align__(8) float2 s_F[NR];            // bin slab, 4KB
    __shared__ float  s_K[64];
    __shared__ float  s_p[512];
    __shared__ double s_red[8];
    __shared__ bool   s_last;

    int tid  = threadIdx.x;
    int bid  = blockIdx.x;
    int lane = tid & 31, wid = tid >> 5;

    asm volatile("griddepcontrol.wait;" ::: "memory"); // k_pre done

    // ================= Phase B: DFT of rows r0..r0+3 =================
    float mn  = __uint_as_float(g_minbits);
    float mx  = __uint_as_float(g_maxbits);
    float inv = 1.0f / (mx - mn);
    float nb  = -mn * inv;

    int r0 = bid * 4;
    if (tid < 256) s_f[tid] = fmaf(g_a[r0 * 64 + tid], inv, nb);
    __syncthreads();

    {
        int ridx = tid >> 7;                           // local row 0..3
        int rem  = tid & 127;
        int k    = rem >> 1;                           // bin 0..63
        int half = rem & 1;                            // x half 0/1
        const float* fr = s_f + ridx * 64;

        float step = -STEP128 * (float)k;
        float sw, cw;
        sincosf(step, &sw, &cw);
        float ci, cr;
        sincosf(step * (float)(half * 32), &ci, &cr);  // phase at x0 = half*32

        float are = 0.0f, aim = 0.0f;
        int x0 = half * 32;
        #pragma unroll 16
        for (int j = 0; j < 32; j++) {
            float fv = fr[x0 + j];
            are = fmaf(fv, cr, are);
            aim = fmaf(fv, ci, aim);
            rot(cr, ci, cw, sw);
        }
        are += __shfl_xor_sync(0xffffffffu, are, 1);
        aim += __shfl_xor_sync(0xffffffffu, aim, 1);
        if (half == 0) g_F[k * NR + (r0 + ridx)] = make_float2(are, aim);

        if (rem == 1) {                                // Nyquist bin
            float s = 0.0f;
            #pragma unroll 16
            for (int x = 0; x < 64; x += 2) s += fr[x] - fr[x + 1];
            g_F[64 * NR + (r0 + ridx)] = make_float2(s, 0.0f);
        }
    }
    __threadfence();
    __syncthreads();
    if (tid == 0) atomicAdd(&g_cnt_dft, 1u);

    if (bid >= NKB) return;                            // 65 blocks continue
    int k = bid;

    // ===== Khat column (g_dtab gather + rotation; overlaps DFT tails) =====
    {
        int dy = tid >> 3, q = tid & 7;                // 8 threads per dy
        float step = STEP128 * (float)k;
        float sw, cw;
        sincosf(step, &sw, &cw);
        float ci, cr;
        sincosf(step * (float)(q * 16), &ci, &cr);

        float acc = 0.0f;
        int n0 = q * 16;
        #pragma unroll 16
        for (int j = 0; j < 16; j++) {
            int n   = n0 + j;
            int dxa = (n < 64) ? n : 128 - n;          // |dx|
            float Kn = (n == 64) ? 0.0f : g_dtab[dy * 64 + dxa];
            acc = fmaf(Kn, cr, acc);
            rot(cr, ci, cw, sw);
        }
        s_p[tid] = acc;
    }
    __syncthreads();
    if (tid < 64) {
        float kv = 0.0f;
        #pragma unroll
        for (int q = 0; q < 8; q++) kv += s_p[tid * 8 + q];
        s_K[tid] = ((tid == 0) ? 1.0f : 2.0f) * kv;    // w_dy
    }

    // ===== spin until all 128 DFT blocks committed =====
    if (tid == 0) {
        while (atomicAdd(&g_cnt_dft, 0u) < (unsigned)SPEC_BLKS) { }
    }
    __syncthreads();

    s_F[tid] = __ldcg(&g_F[k * NR + tid]);             // 512 float2, one each
    __syncthreads();

    // ===== correlation over row pairs with gap dy =====
    int dy = tid & 63;
    int h  = tid >> 6;                                 // iy eighth 0..7
    int iy_lo = h * 8;
    int iy_hi = min(iy_lo + 8, 64 - dy);

    float acc = 0.0f;
    #pragma unroll
    for (int b = 0; b < 8; b++) {
        int base = b * 64;
        for (int iy = iy_lo; iy < iy_hi; iy++) {
            float2 F1 = s_F[base + iy];
            float2 F2 = s_F[base + iy + dy];
            acc = fmaf(F1.x, F2.x, acc);
            acc = fmaf(F1.y, F2.y, acc);
        }
    }
    s_p[tid] = acc;
    __syncthreads();

    double pv = 0.0;
    if (tid < 64) {
        float v = 0.0f;
        #pragma unroll
        for (int hh = 0; hh < 8; hh++) v += s_p[tid + 64 * hh];
        pv = (double)s_K[tid] * (double)v;             // tid = dy
        #pragma unroll
        for (int o = 16; o; o >>= 1)
            pv += __shfl_xor_sync(0xffffffffu, pv, o);
        if (lane == 0) s_red[wid] = pv;
    }
    __syncthreads();
    if (tid == 0) {
        float wk = (k == 0 || k == 64) ? 1.0f : 2.0f;  // conjugate-symmetry weight
        g_partc[k] = (s_red[0] + s_red[1]) * (double)wk;
        __threadfence();
        s_last = (atomicAdd(&g_cnt_fin, 1u) == NKB - 1u);
    }
    __syncthreads();

    // ===== last corr block: fixed-order reduce over the 65 bin scalars =====
    if (s_last) {
        double s = (tid < NKB) ? ((volatile double*)g_partc)[tid] : 0.0;
        #pragma unroll
        for (int o = 16; o; o >>= 1)
            s += __shfl_xor_sync(0xffffffffu, s, o);
        if (lane == 0) s_red[wid] = s;
        __syncthreads();
        if (tid == 0) {
            double t = 0.0;
            #pragma unroll
            for (int w = 0; w < 8; w++) t += s_red[w];
            // / 128 (Parseval) / (B*N*N = 134217728)
            out[0] = (float)(t * (1.0 / (128.0 * 134217728.0)));
            g_cnt_dft = 0;                             // all spins passed by now
            g_cnt_fin = 0;
            g_minbits = 0x7F800000u;
            g_maxbits = 0u;
        }
    }
}

extern "C" void kernel_launch(void* const* d_in, const int* in_sizes, int n_in,
                              void* d_out, int out_size) {
    const float4* in4 = (const float4*)d_in[0];
    float*        out = (float*)d_out;

    k_pre<<<PRE_BLKS, 64>>>(in4);

    cudaLaunchAttribute attr[1];
    attr[0].id = cudaLaunchAttributeProgrammaticStreamSerialization;
    attr[0].val.programmaticStreamSerializationAllowed = 1;

    cudaLaunchConfig_t cfg = {};
    cfg.gridDim  = dim3(SPEC_BLKS);
    cfg.blockDim = dim3(512);
    cfg.attrs    = attr;
    cfg.numAttrs = 1;
    cudaLaunchKernelEx(&cfg, k_spec, out);
}